// round 3
// baseline (speedup 1.0000x reference)
#include <cuda_runtime.h>

// out[b,o] = ( x @ softmax(W,axis=1)^T > 0.5 )
// Strategy: BIT-REPLICATE the reference pipeline (XLA-GPU softmax + cuBLAS SIMT
// SGEMM serial-k fp32 FMA chain), since the pass threshold (<=4 bit flips out of
// 8.4M) is tighter than the reference's own rounding noise (~31 borderline outputs).
//
// d_in[0] = x [4096,2048] f32 (0/1), d_in[1] = raw_weight [2048,2048] f32
// output f32 [4096,2048] of 0/1.

#define M_DIM 4096
#define N_DIM 2048
#define K_DIM 2048

__device__ float g_w[(size_t)N_DIM * K_DIM];  // softmax(W) rows, fp32 bits matching XLA

// ---------------------------------------------------------------------------
// Kernel 1: replicate XLA-GPU softmax row kernel.
//   m = rowmax (exact, order-free)
//   e_i = expf(w_i - m)                      (libdevice __nv_expf, same as XLA)
//   S = XLA row-reduction order: 1024 threads, vec2 partial e[2t]+e[2t+1],
//       shfl_down butterfly (16,8,4,2,1), 32 warp partials, warp0 butterfly.
//   w_i = e_i / S                            (div.rn.f32)
// One block of 1024 threads per row.
// ---------------------------------------------------------------------------
__global__ __launch_bounds__(1024) void softmax_rows_kernel(const float* __restrict__ raw) {
    const int row = blockIdx.x;
    const int tid = threadIdx.x;
    const int lane = tid & 31;
    const int wid = tid >> 5;

    const float2* __restrict__ r2 =
        reinterpret_cast<const float2*>(raw + (size_t)row * K_DIM);
    float2* __restrict__ w2 = reinterpret_cast<float2*>(g_w + (size_t)row * K_DIM);

    const float2 v = r2[tid];

    __shared__ float s_part[32];
    __shared__ float s_bcast;

    // ---- row max (exact in any order) ----
    float m = fmaxf(v.x, v.y);
#pragma unroll
    for (int off = 16; off > 0; off >>= 1)
        m = fmaxf(m, __shfl_down_sync(0xffffffffu, m, off));
    if (lane == 0) s_part[wid] = m;
    __syncthreads();
    if (wid == 0) {
        float t = s_part[lane];
#pragma unroll
        for (int off = 16; off > 0; off >>= 1)
            t = fmaxf(t, __shfl_down_sync(0xffffffffu, t, off));
        if (lane == 0) s_bcast = t;
    }
    __syncthreads();
    m = s_bcast;
    __syncthreads();  // protect s_bcast before reuse below

    // ---- exp (must be precise expf == libdevice __nv_expf) ----
    const float e0 = expf(v.x - m);
    const float e1 = expf(v.y - m);

    // ---- sum, replicating XLA's tree exactly ----
    float p = e0 + e1;  // fl(fl(0+e0)+e1) == fl(e0+e1)
#pragma unroll
    for (int off = 16; off > 0; off >>= 1)
        p += __shfl_down_sync(0xffffffffu, p, off);
    if (lane == 0) s_part[wid] = p;
    __syncthreads();
    if (wid == 0) {
        float t = s_part[lane];  // exactly 32 warp partials
#pragma unroll
        for (int off = 16; off > 0; off >>= 1)
            t += __shfl_down_sync(0xffffffffu, t, off);
        if (lane == 0) s_bcast = t;
    }
    __syncthreads();
    const float S = s_bcast;

    // ---- divide (div.rn.f32 under default nvcc flags) ----
    float2 w;
    w.x = e0 / S;
    w.y = e1 / S;
    w2[tid] = w;
}

// ---------------------------------------------------------------------------
// Kernel 2: C[m,n] = (sum_k A[m,k]*B[n,k] > 0.5) ? 1 : 0
// Accumulation: single fp32 register per output, one FFMA per term, k strictly
// ascending — bit-identical chain to cuBLAS SIMT SGEMM given identical inputs.
// 128x128 tile, BK=16, 256 threads, 8x8 microtile, double-buffered smem.
// ---------------------------------------------------------------------------
#define BM 128
#define BN 128
#define BK 16
#define LDA (BM + 4)
#define NKT (K_DIM / BK)

__global__ __launch_bounds__(256, 2) void gemm_thresh_kernel(const float* __restrict__ A,
                                                             float* __restrict__ C) {
    const float* __restrict__ B = g_w;

    __shared__ float As[2][BK][LDA];
    __shared__ float Bs[2][BK][LDA];

    const int tid = threadIdx.x;
    const int bm = blockIdx.y * BM;
    const int bn = blockIdx.x * BN;

    const int lrow0 = tid >> 2;
    const int lrow1 = lrow0 + 64;
    const int lcol = (tid & 3) * 4;

    const int ty = tid >> 4;
    const int tx = tid & 15;

    float acc[8][8];
#pragma unroll
    for (int i = 0; i < 8; ++i)
#pragma unroll
        for (int j = 0; j < 8; ++j) acc[i][j] = 0.f;

    const float* __restrict__ Ap0 = A + (size_t)(bm + lrow0) * K_DIM + lcol;
    const float* __restrict__ Ap1 = A + (size_t)(bm + lrow1) * K_DIM + lcol;
    const float* __restrict__ Bp0 = B + (size_t)(bn + lrow0) * K_DIM + lcol;
    const float* __restrict__ Bp1 = B + (size_t)(bn + lrow1) * K_DIM + lcol;

    float4 pa0 = *(const float4*)(Ap0);
    float4 pa1 = *(const float4*)(Ap1);
    float4 pb0 = *(const float4*)(Bp0);
    float4 pb1 = *(const float4*)(Bp1);

    int buf = 0;
    As[0][lcol + 0][lrow0] = pa0.x; As[0][lcol + 1][lrow0] = pa0.y;
    As[0][lcol + 2][lrow0] = pa0.z; As[0][lcol + 3][lrow0] = pa0.w;
    As[0][lcol + 0][lrow1] = pa1.x; As[0][lcol + 1][lrow1] = pa1.y;
    As[0][lcol + 2][lrow1] = pa1.z; As[0][lcol + 3][lrow1] = pa1.w;
    Bs[0][lcol + 0][lrow0] = pb0.x; Bs[0][lcol + 1][lrow0] = pb0.y;
    Bs[0][lcol + 2][lrow0] = pb0.z; Bs[0][lcol + 3][lrow0] = pb0.w;
    Bs[0][lcol + 0][lrow1] = pb1.x; Bs[0][lcol + 1][lrow1] = pb1.y;
    Bs[0][lcol + 2][lrow1] = pb1.z; Bs[0][lcol + 3][lrow1] = pb1.w;
    __syncthreads();

    for (int kt = 0; kt < NKT; ++kt) {
        const int ko = (kt + 1) * BK;
        const bool has_next = (kt + 1 < NKT);
        if (has_next) {
            pa0 = *(const float4*)(Ap0 + ko);
            pa1 = *(const float4*)(Ap1 + ko);
            pb0 = *(const float4*)(Bp0 + ko);
            pb1 = *(const float4*)(Bp1 + ko);
        }

#pragma unroll
        for (int k = 0; k < BK; ++k) {  // k strictly ascending: serial FMA chain
            float4 a0 = *(const float4*)&As[buf][k][ty * 4];
            float4 a1 = *(const float4*)&As[buf][k][64 + ty * 4];
            float4 b0 = *(const float4*)&Bs[buf][k][tx * 4];
            float4 b1 = *(const float4*)&Bs[buf][k][64 + tx * 4];
            float av[8] = {a0.x, a0.y, a0.z, a0.w, a1.x, a1.y, a1.z, a1.w};
            float bv[8] = {b0.x, b0.y, b0.z, b0.w, b1.x, b1.y, b1.z, b1.w};
#pragma unroll
            for (int i = 0; i < 8; ++i)
#pragma unroll
                for (int j = 0; j < 8; ++j) acc[i][j] += av[i] * bv[j];
        }

        if (has_next) {
            buf ^= 1;
            As[buf][lcol + 0][lrow0] = pa0.x; As[buf][lcol + 1][lrow0] = pa0.y;
            As[buf][lcol + 2][lrow0] = pa0.z; As[buf][lcol + 3][lrow0] = pa0.w;
            As[buf][lcol + 0][lrow1] = pa1.x; As[buf][lcol + 1][lrow1] = pa1.y;
            As[buf][lcol + 2][lrow1] = pa1.z; As[buf][lcol + 3][lrow1] = pa1.w;
            Bs[buf][lcol + 0][lrow0] = pb0.x; Bs[buf][lcol + 1][lrow0] = pb0.y;
            Bs[buf][lcol + 2][lrow0] = pb0.z; Bs[buf][lcol + 3][lrow0] = pb0.w;
            Bs[buf][lcol + 0][lrow1] = pb1.x; Bs[buf][lcol + 1][lrow1] = pb1.y;
            Bs[buf][lcol + 2][lrow1] = pb1.z; Bs[buf][lcol + 3][lrow1] = pb1.w;
            __syncthreads();
        }
    }

    // Epilogue: threshold at 0.5 (same compare as reference).
#pragma unroll
    for (int i = 0; i < 8; ++i) {
        const int m = bm + ((i < 4) ? (ty * 4 + i) : (64 + ty * 4 + (i - 4)));
        float4 o0, o1;
        o0.x = acc[i][0] > 0.5f ? 1.f : 0.f;
        o0.y = acc[i][1] > 0.5f ? 1.f : 0.f;
        o0.z = acc[i][2] > 0.5f ? 1.f : 0.f;
        o0.w = acc[i][3] > 0.5f ? 1.f : 0.f;
        o1.x = acc[i][4] > 0.5f ? 1.f : 0.f;
        o1.y = acc[i][5] > 0.5f ? 1.f : 0.f;
        o1.z = acc[i][6] > 0.5f ? 1.f : 0.f;
        o1.w = acc[i][7] > 0.5f ? 1.f : 0.f;
        *(float4*)&C[(size_t)m * N_DIM + bn + tx * 4] = o0;
        *(float4*)&C[(size_t)m * N_DIM + bn + 64 + tx * 4] = o1;
    }
}

// ---------------------------------------------------------------------------
extern "C" void kernel_launch(void* const* d_in, const int* in_sizes, int n_in,
                              void* d_out, int out_size) {
    const float* x = (const float*)d_in[0];      // [4096, 2048]
    const float* raw_w = (const float*)d_in[1];  // [2048, 2048]
    float* out = (float*)d_out;                  // [4096, 2048]

    softmax_rows_kernel<<<N_DIM, 1024>>>(raw_w);

    dim3 grid(N_DIM / BN, M_DIM / BM);  // (16, 32)
    gemm_thresh_kernel<<<grid, 256>>>(x, out);
}

// round 4
// speedup vs baseline: 1.0004x; 1.0004x over previous
#include <cuda_runtime.h>

// out[b,o] = ( x @ softmax(W,axis=1)^T > 0.5 )
// BIT-REPLICATION constraint: softmax must match XLA's row-reduction tree;
// GEMM must be a serial ascending-k fp32 FFMA chain per output (matches the
// reference's SIMT SGEMM). Verified: 1 bit flip @ rel_err 4.9e-4 (pass).
//
// d_in[0] = x [4096,2048] f32 (0/1), d_in[1] = raw_weight [2048,2048] f32
// output f32 [4096,2048] of 0/1.

#define M_DIM 4096
#define N_DIM 2048
#define K_DIM 2048

__device__ float g_w[(size_t)N_DIM * K_DIM];  // softmax(W), bit-matching reference

// ---------------------------------------------------------------------------
// Kernel 1: XLA-GPU softmax row kernel replica (1024 thr/row, vec2, shfl_down
// butterfly, 32 warp partials, warp0 butterfly, div.rn).  DO NOT CHANGE ORDER.
// ---------------------------------------------------------------------------
__global__ __launch_bounds__(1024) void softmax_rows_kernel(const float* __restrict__ raw) {
    const int row = blockIdx.x;
    const int tid = threadIdx.x;
    const int lane = tid & 31;
    const int wid = tid >> 5;

    const float2* __restrict__ r2 =
        reinterpret_cast<const float2*>(raw + (size_t)row * K_DIM);
    float2* __restrict__ w2 = reinterpret_cast<float2*>(g_w + (size_t)row * K_DIM);

    const float2 v = r2[tid];

    __shared__ float s_part[32];
    __shared__ float s_bcast;

    float m = fmaxf(v.x, v.y);
#pragma unroll
    for (int off = 16; off > 0; off >>= 1)
        m = fmaxf(m, __shfl_down_sync(0xffffffffu, m, off));
    if (lane == 0) s_part[wid] = m;
    __syncthreads();
    if (wid == 0) {
        float t = s_part[lane];
#pragma unroll
        for (int off = 16; off > 0; off >>= 1)
            t = fmaxf(t, __shfl_down_sync(0xffffffffu, t, off));
        if (lane == 0) s_bcast = t;
    }
    __syncthreads();
    m = s_bcast;
    __syncthreads();

    const float e0 = expf(v.x - m);
    const float e1 = expf(v.y - m);

    float p = e0 + e1;
#pragma unroll
    for (int off = 16; off > 0; off >>= 1)
        p += __shfl_down_sync(0xffffffffu, p, off);
    if (lane == 0) s_part[wid] = p;
    __syncthreads();
    if (wid == 0) {
        float t = s_part[lane];
#pragma unroll
        for (int off = 16; off > 0; off >>= 1)
            t += __shfl_down_sync(0xffffffffu, t, off);
        if (lane == 0) s_bcast = t;
    }
    __syncthreads();
    const float S = s_bcast;

    float2 w;
    w.x = e0 / S;
    w.y = e1 / S;
    w2[tid] = w;
}

// ---------------------------------------------------------------------------
// Kernel 2: C[m,n] = (sum_k A[m,k]*B[n,k] > 0.5) ? 1 : 0
// 128x128 tile, BK=16, 256 threads, 8x8 microtile, double-buffered smem.
// Inner FFMAs reference float4 components DIRECTLY (no staging arrays) to
// eliminate the 16 MOVs/k-step ptxas emitted for av[]/bv[].
// ---------------------------------------------------------------------------
#define BM 128
#define BN 128
#define BK 16
#define LDA (BM + 4)
#define NKT (K_DIM / BK)

// One M-row of the 8x8 microtile: 8 FFMAs against b0/b1 components.
#define FMA_ROW(i, aval)                 \
    acc[i][0] += (aval) * b0.x;          \
    acc[i][1] += (aval) * b0.y;          \
    acc[i][2] += (aval) * b0.z;          \
    acc[i][3] += (aval) * b0.w;          \
    acc[i][4] += (aval) * b1.x;          \
    acc[i][5] += (aval) * b1.y;          \
    acc[i][6] += (aval) * b1.z;          \
    acc[i][7] += (aval) * b1.w;

__global__ __launch_bounds__(256, 2) void gemm_thresh_kernel(const float* __restrict__ A,
                                                             float* __restrict__ C) {
    const float* __restrict__ B = g_w;

    __shared__ float As[2][BK][LDA];
    __shared__ float Bs[2][BK][LDA];

    const int tid = threadIdx.x;
    const int bm = blockIdx.y * BM;
    const int bn = blockIdx.x * BN;

    const int lrow0 = tid >> 2;
    const int lrow1 = lrow0 + 64;
    const int lcol = (tid & 3) * 4;

    const int ty = tid >> 4;
    const int tx = tid & 15;

    float acc[8][8];
#pragma unroll
    for (int i = 0; i < 8; ++i)
#pragma unroll
        for (int j = 0; j < 8; ++j) acc[i][j] = 0.f;

    const float* __restrict__ Ap0 = A + (size_t)(bm + lrow0) * K_DIM + lcol;
    const float* __restrict__ Ap1 = A + (size_t)(bm + lrow1) * K_DIM + lcol;
    const float* __restrict__ Bp0 = B + (size_t)(bn + lrow0) * K_DIM + lcol;
    const float* __restrict__ Bp1 = B + (size_t)(bn + lrow1) * K_DIM + lcol;

    float4 pa0 = *(const float4*)(Ap0);
    float4 pa1 = *(const float4*)(Ap1);
    float4 pb0 = *(const float4*)(Bp0);
    float4 pb1 = *(const float4*)(Bp1);

    int buf = 0;
    As[0][lcol + 0][lrow0] = pa0.x; As[0][lcol + 1][lrow0] = pa0.y;
    As[0][lcol + 2][lrow0] = pa0.z; As[0][lcol + 3][lrow0] = pa0.w;
    As[0][lcol + 0][lrow1] = pa1.x; As[0][lcol + 1][lrow1] = pa1.y;
    As[0][lcol + 2][lrow1] = pa1.z; As[0][lcol + 3][lrow1] = pa1.w;
    Bs[0][lcol + 0][lrow0] = pb0.x; Bs[0][lcol + 1][lrow0] = pb0.y;
    Bs[0][lcol + 2][lrow0] = pb0.z; Bs[0][lcol + 3][lrow0] = pb0.w;
    Bs[0][lcol + 0][lrow1] = pb1.x; Bs[0][lcol + 1][lrow1] = pb1.y;
    Bs[0][lcol + 2][lrow1] = pb1.z; Bs[0][lcol + 3][lrow1] = pb1.w;
    __syncthreads();

    for (int kt = 0; kt < NKT; ++kt) {
        const int ko = (kt + 1) * BK;
        const bool has_next = (kt + 1 < NKT);
        if (has_next) {
            pa0 = *(const float4*)(Ap0 + ko);
            pa1 = *(const float4*)(Ap1 + ko);
            pb0 = *(const float4*)(Bp0 + ko);
            pb1 = *(const float4*)(Bp1 + ko);
        }

#pragma unroll
        for (int k = 0; k < BK; ++k) {  // k strictly ascending: serial FMA chain
            const float4 a0 = *(const float4*)&As[buf][k][ty * 4];
            const float4 a1 = *(const float4*)&As[buf][k][64 + ty * 4];
            const float4 b0 = *(const float4*)&Bs[buf][k][tx * 4];
            const float4 b1 = *(const float4*)&Bs[buf][k][64 + tx * 4];
            FMA_ROW(0, a0.x)
            FMA_ROW(1, a0.y)
            FMA_ROW(2, a0.z)
            FMA_ROW(3, a0.w)
            FMA_ROW(4, a1.x)
            FMA_ROW(5, a1.y)
            FMA_ROW(6, a1.z)
            FMA_ROW(7, a1.w)
        }

        if (has_next) {
            buf ^= 1;
            As[buf][lcol + 0][lrow0] = pa0.x; As[buf][lcol + 1][lrow0] = pa0.y;
            As[buf][lcol + 2][lrow0] = pa0.z; As[buf][lcol + 3][lrow0] = pa0.w;
            As[buf][lcol + 0][lrow1] = pa1.x; As[buf][lcol + 1][lrow1] = pa1.y;
            As[buf][lcol + 2][lrow1] = pa1.z; As[buf][lcol + 3][lrow1] = pa1.w;
            Bs[buf][lcol + 0][lrow0] = pb0.x; Bs[buf][lcol + 1][lrow0] = pb0.y;
            Bs[buf][lcol + 2][lrow0] = pb0.z; Bs[buf][lcol + 3][lrow0] = pb0.w;
            Bs[buf][lcol + 0][lrow1] = pb1.x; Bs[buf][lcol + 1][lrow1] = pb1.y;
            Bs[buf][lcol + 2][lrow1] = pb1.z; Bs[buf][lcol + 3][lrow1] = pb1.w;
            __syncthreads();
        }
    }

#pragma unroll
    for (int i = 0; i < 8; ++i) {
        const int m = bm + ((i < 4) ? (ty * 4 + i) : (64 + ty * 4 + (i - 4)));
        float4 o0, o1;
        o0.x = acc[i][0] > 0.5f ? 1.f : 0.f;
        o0.y = acc[i][1] > 0.5f ? 1.f : 0.f;
        o0.z = acc[i][2] > 0.5f ? 1.f : 0.f;
        o0.w = acc[i][3] > 0.5f ? 1.f : 0.f;
        o1.x = acc[i][4] > 0.5f ? 1.f : 0.f;
        o1.y = acc[i][5] > 0.5f ? 1.f : 0.f;
        o1.z = acc[i][6] > 0.5f ? 1.f : 0.f;
        o1.w = acc[i][7] > 0.5f ? 1.f : 0.f;
        *(float4*)&C[(size_t)m * N_DIM + bn + tx * 4] = o0;
        *(float4*)&C[(size_t)m * N_DIM + bn + 64 + tx * 4] = o1;
    }
}

// ---------------------------------------------------------------------------
extern "C" void kernel_launch(void* const* d_in, const int* in_sizes, int n_in,
                              void* d_out, int out_size) {
    const float* x = (const float*)d_in[0];      // [4096, 2048]
    const float* raw_w = (const float*)d_in[1];  // [2048, 2048]
    float* out = (float*)d_out;                  // [4096, 2048]

    softmax_rows_kernel<<<N_DIM, 1024>>>(raw_w);

    dim3 grid(N_DIM / BN, M_DIM / BM);  // (16, 32)
    gemm_thresh_kernel<<<grid, 256>>>(x, out);
}